// round 16
// baseline (speedup 1.0000x reference)
#include <cuda_runtime.h>

#define Bb   8
#define HW   1024
#define Cc   512
#define C4   128
#define NBLK 128
#define NTHR 512
#define DYN_BYTES (64 * 1024 + 32 * 1024)   // wbuf (64KB) + psum (32KB)

// ---------------- sync state: one counter per 128-B line ---------------------
struct alignas(128) Line { unsigned v; unsigned pad[31]; };
__device__ Line c_cs[8];    // colsum tickets per batch (16 each; 16th reduces)
__device__ Line c_xs;       // xsum winners (8)
__device__ Line cnt2[4];    // P2b arrivals (32)
__device__ Line cnt3[4];    // P3 arrivals (32)
__device__ Line cnt4[2];    // P4 arrivals (16, 8/line)
__device__ Line cnt6[1];    // P5 arrivals (16)
__device__ Line cnt7[8];    // epilogue arrivals, per batch (16 each)
__device__ Line c_fin;      // 128 arrivals; 128th resets (never polled)
__device__ unsigned g_mnk[Bb] = {0xFFFFFFFFu,0xFFFFFFFFu,0xFFFFFFFFu,0xFFFFFFFFu,
                                 0xFFFFFFFFu,0xFFFFFFFFu,0xFFFFFFFFu,0xFFFFFFFFu};
__device__ unsigned g_mxk[Bb] = {0,0,0,0,0,0,0,0};

// ---------------- data scratch (fully rewritten every launch) ----------------
__device__ __align__(16) float4 g_partial[Bb][16][C4];
__device__ __align__(16) float  g_xsum[Bb][Cc];
__device__ __align__(16) float  g_xr[Bb][Cc];
__device__ __align__(16) float  g_ksum[Bb][Cc];
__device__ __align__(16) float  g_wpart[16][Bb][Cc];
__device__ __align__(16) float  g_w[Bb][Cc];
__device__ __align__(16) float  g_upart[16][Bb][Cc];

__device__ __forceinline__ unsigned ldv(const unsigned* p) {
    return *(volatile const unsigned*)p;
}
__device__ __forceinline__ unsigned enc(float f) {
    unsigned u = __float_as_uint(f);
    return (u & 0x80000000u) ? ~u : (u | 0x80000000u);
}
__device__ __forceinline__ float dec(unsigned k) {
    return (k & 0x80000000u) ? __uint_as_float(k ^ 0x80000000u)
                             : __uint_as_float(~k);
}

// arrive: t==0 (after block sync) releases + bumps one line
#define ARRIVE_LINE(lineptr)                                          \
    do { __syncthreads();                                             \
         if (t == 0) { __threadfence(); atomicAdd(&(lineptr)->v, 1u); } \
    } while (0)
// wait until sum of n lines >= tgt
#define WAIT_LINES(arr, n, tgt)                                       \
    do { if (t == 0) {                                                \
             unsigned s_;                                             \
             do { s_ = 0;                                             \
                  _Pragma("unroll")                                   \
                  for (int i_ = 0; i_ < (n); ++i_) s_ += ldv(&(arr)[i_].v); \
             } while (s_ < (unsigned)(tgt));                          \
             __threadfence();                                         \
         }                                                            \
         __syncthreads();                                             \
    } while (0)

__global__ void __launch_bounds__(NTHR)
fused_kernel(const float* __restrict__ x,
             const float* __restrict__ conv_w, const float* __restrict__ conv_b,
             const float* __restrict__ q_w,
             const float* __restrict__ k_w,    const float* __restrict__ k_b,
             float* __restrict__ out)
{
    extern __shared__ float dynsh[];
    float* wbuf = dynsh;                         // 16384 floats (64 KB)
    float* psum = dynsh + 16384;                 // 8192 floats (32 KB): [64][128]
    __shared__ __align__(16) float shA[Bb][Cc];  // 16 KB
    __shared__ __align__(16) float shB[Cc];      // 2 KB
    __shared__ float sdot[64];
    __shared__ float shW[Bb][32];
    __shared__ unsigned sh_tk;

    const int g    = blockIdx.x;
    const int t    = threadIdx.x;
    const int warp = t >> 5, lane = t & 31;
    const int b_own = g >> 4, s_own = g & 15;
    const int c4 = t & 127, rs = t >> 7;

    // ================= P1: x tile -> REGISTERS (+colsum) & weight prefetch ===
    float4 xreg[16];
    {
        const float4* base = reinterpret_cast<const float4*>(x)
                           + ((size_t)(b_own * HW + s_own * 64 + rs * 16)) * C4 + c4;
        float4 acc = make_float4(0.f, 0.f, 0.f, 0.f);
#pragma unroll
        for (int p = 0; p < 16; ++p) {
            xreg[p] = base[(size_t)p * C4];
            acc.x += xreg[p].x; acc.y += xreg[p].y;
            acc.z += xreg[p].z; acc.w += xreg[p].w;
        }
        float4* shP = reinterpret_cast<float4*>(shA);   // [4][128]
        shP[rs * C4 + c4] = acc;

        // weight prefetch into smem (overlaps x loads)
        float4* wb4 = reinterpret_cast<float4*>(wbuf);
        if (g >= 32 && g < 64) {            // A: conv_w rows [(g-32)*16, +16)
            const float4* src = reinterpret_cast<const float4*>(conv_w) + (g - 32) * 2048;
#pragma unroll
            for (int i = 0; i < 4; ++i) wb4[t + i * NTHR] = src[t + i * NTHR];
        } else if (g >= 64 && g < 96) {     // B: k_w rows [(g-64)*16, +16)
            const float4* src = reinterpret_cast<const float4*>(k_w) + (g - 64) * 2048;
#pragma unroll
            for (int i = 0; i < 4; ++i) wb4[t + i * NTHR] = src[t + i * NTHR];
        } else if (g < 16) {                // C: q_w rows [g*32, +32)
            const float4* src = reinterpret_cast<const float4*>(q_w) + g * 4096;
#pragma unroll
            for (int i = 0; i < 8; ++i) wb4[t + i * NTHR] = src[t + i * NTHR];
        } else if (g >= 16 && g < 32) {     // D: conv_w rows [(g-16)*32, +32)
            const float4* src = reinterpret_cast<const float4*>(conv_w) + (g - 16) * 4096;
#pragma unroll
            for (int i = 0; i < 8; ++i) wb4[t + i * NTHR] = src[t + i * NTHR];
        }
        __syncthreads();
        if (t < C4) {
            float4* shP2 = reinterpret_cast<float4*>(shA);
            float4 a = shP2[t], p1 = shP2[C4 + t], p2 = shP2[2 * C4 + t], p3 = shP2[3 * C4 + t];
            a.x += p1.x + p2.x + p3.x;  a.y += p1.y + p2.y + p3.y;
            a.z += p1.z + p2.z + p3.z;  a.w += p1.w + p2.w + p3.w;
            g_partial[b_own][s_own][t] = a;
        }
    }
    // colsum ticket: 16th block of each batch reduces Xsum (fixed order)
    __syncthreads();
    if (t == 0) { __threadfence(); sh_tk = atomicAdd(&c_cs[b_own].v, 1u); }
    __syncthreads();
    if (sh_tk == 15u) {
        __threadfence();                    // see other blocks' partials
        const float* gp = &g_partial[0][0][0].x;
        float a = 0.f;
#pragma unroll
        for (int sp = 0; sp < 16; ++sp)
            a += gp[(b_own * 16 + sp) * Cc + t];
        g_xsum[b_own][t] = a;
        __syncthreads();
        if (t == 0) { __threadfence(); atomicAdd(&c_xs.v, 1u); }
    }

    // ================= group A (32..63): conv matvec (xr) ====================
    if (g >= 32 && g < 64) {
        const int a = g - 32;
        WAIT_LINES(&c_xs, 1, 8);
        {   // P2b: xr = conv_w @ Xsum + HW*conv_b + Xsum
            float4* shA4 = reinterpret_cast<float4*>(shA);
            const float4* gx4 = reinterpret_cast<const float4*>(g_xsum);
#pragma unroll
            for (int i = 0; i < 2; ++i) shA4[t + i * NTHR] = gx4[t + i * NTHR];
            __syncthreads();

            const int o = a * 16 + warp;
            float acc[Bb];
#pragma unroll
            for (int b = 0; b < Bb; ++b) acc[b] = 0.f;
#pragma unroll
            for (int k = 0; k < 16; ++k) {
                const int c = lane + 32 * k;
                const float wv = wbuf[warp * Cc + c];
#pragma unroll
                for (int b = 0; b < Bb; ++b) acc[b] += wv * shA[b][c];
            }
#pragma unroll
            for (int b = 0; b < Bb; ++b)
#pragma unroll
                for (int off = 16; off; off >>= 1)
                    acc[b] += __shfl_xor_sync(0xffffffffu, acc[b], off);
            if (lane == 0) {
                const float cb = (float)HW * conv_b[o];
#pragma unroll
                for (int b = 0; b < Bb; ++b)
                    g_xr[b][o] = acc[b] + cb + shA[b][o];
            }
        }
        ARRIVE_LINE(&cnt2[a & 3]);
    }

    // ================= group B (64..95): Ksum matvec =========================
    if (g >= 64 && g < 96) {
        const int bbk = g - 64;
        WAIT_LINES(cnt2, 4, 32);
        {
            float4* shA4 = reinterpret_cast<float4*>(shA);
            const float4* gxr4 = reinterpret_cast<const float4*>(g_xr);
#pragma unroll
            for (int i = 0; i < 2; ++i) shA4[t + i * NTHR] = gxr4[t + i * NTHR];
            __syncthreads();

            const int o = bbk * 16 + warp;
            float acc[Bb];
#pragma unroll
            for (int b = 0; b < Bb; ++b) acc[b] = 0.f;
#pragma unroll
            for (int k = 0; k < 16; ++k) {
                const int c = lane + 32 * k;
                const float wv = wbuf[warp * Cc + c];
#pragma unroll
                for (int b = 0; b < Bb; ++b) acc[b] += wv * shA[b][c];
            }
#pragma unroll
            for (int b = 0; b < Bb; ++b)
#pragma unroll
                for (int off = 16; off; off >>= 1)
                    acc[b] += __shfl_xor_sync(0xffffffffu, acc[b], off);
            if (lane == 0) {
                const float kb = (float)HW * k_b[o];
#pragma unroll
                for (int b = 0; b < Bb; ++b)
                    g_ksum[b][o] = acc[b] + kb;
            }
        }
        ARRIVE_LINE(&cnt3[bbk & 3]);
    }

    // ================= group C (0..15): w partials ===========================
    if (g < 16) {
        WAIT_LINES(cnt3, 4, 32);
        float tot = 0.f;
#pragma unroll
        for (int b = 0; b < Bb; ++b) tot += g_ksum[b][t];
        shB[t] = tot;
        __syncthreads();
#pragma unroll
        for (int i = 0; i < Bb; ++i) {
            const int idx = t + i * NTHR;
            const int b = idx >> 9, c = idx & 511;
            shA[b][c] = shB[c] - g_ksum[b][c];
        }
        __syncthreads();

        float acc[Bb];
#pragma unroll
        for (int b = 0; b < Bb; ++b) acc[b] = 0.f;
#pragma unroll
        for (int oo = 0; oo < 32; ++oo) {
            const int o = g * 32 + oo;
            const float wv = wbuf[oo * Cc + t];
#pragma unroll
            for (int b = 0; b < Bb; ++b) acc[b] += wv * shA[b][o];
        }
#pragma unroll
        for (int b = 0; b < Bb; ++b) g_wpart[g][b][t] = acc[b];
        ARRIVE_LINE(&cnt4[g & 1]);
    }

    // ================= group D (16..31): w reduce (o-chunk) + u partial ======
    if (g >= 16 && g < 32) {
        const int j = g - 16;
        WAIT_LINES(cnt4, 2, 16);
        {   // inline reduce of w over its o-chunk [j*32, +32), all b
            const int p = t >> 1, h = t & 1;       // p: 0..255 = (b,oo)
            const int b = p >> 5, oo = p & 31;
            float s = 0.f;
#pragma unroll
            for (int jj = 0; jj < 8; ++jj)
                s += g_wpart[h * 8 + jj][b][j * 32 + oo];
            s += __shfl_xor_sync(0xffffffffu, s, 1);
            if (h == 0) { shW[b][oo] = s; g_w[b][j * 32 + oo] = s; }
            __syncthreads();
        }
        {   // u partial: conv_w^T over o-chunk
            float acc[Bb];
#pragma unroll
            for (int b = 0; b < Bb; ++b) acc[b] = 0.f;
#pragma unroll
            for (int oo = 0; oo < 32; ++oo) {
                const float wv = wbuf[oo * Cc + t];
#pragma unroll
                for (int b = 0; b < Bb; ++b) acc[b] += wv * shW[b][oo];
            }
#pragma unroll
            for (int b = 0; b < Bb; ++b) g_upart[j][b][t] = acc[b];
        }
        ARRIVE_LINE(&cnt6[0]);
    }

    // ================= all blocks: P6 dot + epilogue =========================
    WAIT_LINES(cnt6, 1, 16);
    {
        // u[t] = sum_j upart[j][b][t] + w[b][t]   (the +w residual term)
        float a = g_w[b_own][t];
#pragma unroll
        for (int jj = 0; jj < 16; ++jj) a += g_upart[jj][b_own][t];
        shB[t] = a;
        __syncthreads();

        const float4 uv = reinterpret_cast<const float4*>(shB)[c4];
#pragma unroll
        for (int p = 0; p < 16; ++p) {
            const float4 xv = xreg[p];
            psum[(rs * 16 + p) * C4 + c4] =
                xv.x * uv.x + xv.y * uv.y + xv.z * uv.z + xv.w * uv.w;
        }
        __syncthreads();

        // row reduce: warp handles 4 rows, 128 partials each
#pragma unroll
        for (int rr = 0; rr < 4; ++rr) {
            const int row = warp * 4 + rr;
            float s = psum[row * C4 + lane] + psum[row * C4 + lane + 32]
                    + psum[row * C4 + lane + 64] + psum[row * C4 + lane + 96];
#pragma unroll
            for (int off = 16; off; off >>= 1)
                s += __shfl_xor_sync(0xffffffffu, s, off);
            if (lane == 0) sdot[row] = s;
        }
    }
    __syncthreads();
    if (warp == 0) {
        float v0 = sdot[lane], v1 = sdot[lane + 32];
        float mn = fminf(v0, v1), mx = fmaxf(v0, v1);
#pragma unroll
        for (int off = 16; off; off >>= 1) {
            mn = fminf(mn, __shfl_xor_sync(0xffffffffu, mn, off));
            mx = fmaxf(mx, __shfl_xor_sync(0xffffffffu, mx, off));
        }
        if (lane == 0) {
            atomicMin(&g_mnk[b_own], enc(mn));
            atomicMax(&g_mxk[b_own], enc(mx));
        }
    }
    ARRIVE_LINE(&cnt7[b_own]);
    WAIT_LINES(&cnt7[b_own], 1, 16);

    if (t < 64) {
        const float mn = dec(g_mnk[b_own]);
        const float mx = dec(g_mxk[b_own]);
        const float inv = 1.0f / (mx - mn);
        const float z = ((sdot[t] - mn) * inv - 0.65f) / 0.15f;
        out[b_own * HW + s_own * 64 + t] = 1.0f / (1.0f + __expf(-z));
    }

    // ======= tail: never-polled reset — 128th arrival resets everything ======
    __syncthreads();
    if (t == 0) {
        unsigned old = atomicAdd(&c_fin.v, 1u);
        if (old == (unsigned)NBLK - 1u) {
#pragma unroll
            for (int i = 0; i < 8;  ++i) { c_cs[i].v = 0u; cnt7[i].v = 0u; }
#pragma unroll
            for (int i = 0; i < 4;  ++i) { cnt2[i].v = 0u; cnt3[i].v = 0u; }
#pragma unroll
            for (int i = 0; i < 2;  ++i) cnt4[i].v = 0u;
            c_xs.v = 0u; cnt6[0].v = 0u;
            c_fin.v = 0u;
#pragma unroll
            for (int b = 0; b < Bb; ++b) { g_mnk[b] = 0xFFFFFFFFu; g_mxk[b] = 0u; }
            __threadfence();
        }
    }
}

// ---------------------------------------------------------------------------
extern "C" void kernel_launch(void* const* d_in, const int* in_sizes, int n_in,
                              void* d_out, int out_size) {
    const float* x      = (const float*)d_in[0];
    const float* conv_w = (const float*)d_in[1];
    const float* conv_b = (const float*)d_in[2];
    const float* q_w    = (const float*)d_in[3];
    // d_in[4] = q_b: per-batch constant, cancels in min/max normalization.
    const float* k_w    = (const float*)d_in[5];
    const float* k_b    = (const float*)d_in[6];
    float* out = (float*)d_out;

    cudaFuncSetAttribute(fused_kernel,
                         cudaFuncAttributeMaxDynamicSharedMemorySize,
                         DYN_BYTES);
    fused_kernel<<<NBLK, NTHR, DYN_BYTES>>>(x, conv_w, conv_b, q_w, k_w, k_b, out);
}

// round 17
// speedup vs baseline: 1.0565x; 1.0565x over previous
#include <cuda_runtime.h>

#define Bb   8
#define HW   1024
#define Cc   512
#define C4   128
#define NBLK 128
#define NTHR 512
#define DYN_BYTES (64 * 1024 + 32 * 1024)   // wbuf (64KB) + psum (32KB)

// ---------------- sync state: one counter per 128-B line ---------------------
struct alignas(128) Line { unsigned v; unsigned pad[31]; };
__device__ Line cnt0[8];    // P1 arrivals, per batch (16 each)
__device__ Line cnt1[4];    // P2a arrivals (32 total, 8/line)
__device__ Line cnt2[4];    // xr+kp arrivals (32)
__device__ Line cnt4[2];    // wpart arrivals (16, 8/line)
__device__ Line cnt6[1];    // upart arrivals (16)
__device__ Line cnt7[8];    // epilogue arrivals, per batch (16 each)
__device__ Line c_fin;      // 128 arrivals; 128th resets (never polled)
__device__ unsigned g_mnk[Bb] = {0xFFFFFFFFu,0xFFFFFFFFu,0xFFFFFFFFu,0xFFFFFFFFu,
                                 0xFFFFFFFFu,0xFFFFFFFFu,0xFFFFFFFFu,0xFFFFFFFFu};
__device__ unsigned g_mxk[Bb] = {0,0,0,0,0,0,0,0};

// ---------------- data scratch (fully rewritten every launch) ----------------
__device__ __align__(16) float4 g_partial[Bb][16][C4];
__device__ __align__(16) float4 g_xsum4[Bb][C4];
__device__ __align__(16) float  g_kp[32][Bb][Cc];   // ksum c-chunk partials
__device__ __align__(16) float  g_wpart[16][Bb][Cc];
__device__ __align__(16) float  g_w[Bb][Cc];
__device__ __align__(16) float  g_upart[16][Bb][Cc];

__device__ __forceinline__ unsigned ldv(const unsigned* p) {
    return *(volatile const unsigned*)p;
}
__device__ __forceinline__ unsigned enc(float f) {
    unsigned u = __float_as_uint(f);
    return (u & 0x80000000u) ? ~u : (u | 0x80000000u);
}
__device__ __forceinline__ float dec(unsigned k) {
    return (k & 0x80000000u) ? __uint_as_float(k ^ 0x80000000u)
                             : __uint_as_float(~k);
}

#define ARRIVE_LINE(lineptr)                                          \
    do { __syncthreads();                                             \
         if (t == 0) { __threadfence(); atomicAdd(&(lineptr)->v, 1u); } \
    } while (0)
#define WAIT_LINES(arr, n, tgt)                                       \
    do { if (t == 0) {                                                \
             unsigned s_;                                             \
             do { s_ = 0;                                             \
                  _Pragma("unroll")                                   \
                  for (int i_ = 0; i_ < (n); ++i_) s_ += ldv(&(arr)[i_].v); \
             } while (s_ < (unsigned)(tgt));                          \
             __threadfence();                                         \
         }                                                            \
         __syncthreads();                                             \
    } while (0)

__global__ void __launch_bounds__(NTHR)
fused_kernel(const float* __restrict__ x,
             const float* __restrict__ conv_w, const float* __restrict__ conv_b,
             const float* __restrict__ q_w,
             const float* __restrict__ k_w,    const float* __restrict__ k_b,
             float* __restrict__ out)
{
    extern __shared__ float dynsh[];
    float* wbuf = dynsh;                         // 16384 floats (64 KB)
    float* psum = dynsh + 16384;                 // 8192 floats (32 KB): [64][128]
    __shared__ __align__(16) float shA[Bb][Cc];  // 16 KB
    __shared__ __align__(16) float shB[Cc];      // 2 KB
    __shared__ float sdot[64];
    __shared__ float shW[Bb][32];
    __shared__ float sXr[Bb][16];
    __shared__ float sKs[Bb][32];
    __shared__ float sTot[32];
    __shared__ float sV[Bb][32];

    const int g    = blockIdx.x;
    const int t    = threadIdx.x;
    const int warp = t >> 5, lane = t & 31;
    const int b_own = g >> 4, s_own = g & 15;
    const int c4 = t & 127, rs = t >> 7;

    // ================= P1: x tile -> REGISTERS (+colsum) & weight prefetch ===
    float4 xreg[16];
    {
        const float4* base = reinterpret_cast<const float4*>(x)
                           + ((size_t)(b_own * HW + s_own * 64 + rs * 16)) * C4 + c4;
        float4 acc = make_float4(0.f, 0.f, 0.f, 0.f);
#pragma unroll
        for (int p = 0; p < 16; ++p) {
            xreg[p] = base[(size_t)p * C4];
            acc.x += xreg[p].x; acc.y += xreg[p].y;
            acc.z += xreg[p].z; acc.w += xreg[p].w;
        }
        float4* shP = reinterpret_cast<float4*>(shA);   // [4][128]
        shP[rs * C4 + c4] = acc;

        // weight prefetch into smem (overlaps x loads)
        float4* wb4 = reinterpret_cast<float4*>(wbuf);
        if (g >= 32 && g < 64) {            // A: conv rows + k_w COLUMNS (transposed)
            const int a = g - 32;
            const float4* src = reinterpret_cast<const float4*>(conv_w) + a * 2048;
#pragma unroll
            for (int i = 0; i < 4; ++i) wb4[t + i * NTHR] = src[t + i * NTHR];
            // k_w columns [a*16, a*16+16) -> kT[cl][o] at wbuf+8192
            const float4* kw4 = reinterpret_cast<const float4*>(k_w);
#pragma unroll
            for (int i = 0; i < 4; ++i) {
                const int f = t + i * NTHR;          // 0..2047
                const int row = f >> 2, seg = f & 3;
                const float4 v = kw4[row * C4 + a * 4 + seg];
                wbuf[8192 + (seg * 4 + 0) * Cc + row] = v.x;
                wbuf[8192 + (seg * 4 + 1) * Cc + row] = v.y;
                wbuf[8192 + (seg * 4 + 2) * Cc + row] = v.z;
                wbuf[8192 + (seg * 4 + 3) * Cc + row] = v.w;
            }
        } else if (g < 16) {                // C: q_w rows [g*32, +32)
            const float4* src = reinterpret_cast<const float4*>(q_w) + g * 4096;
#pragma unroll
            for (int i = 0; i < 8; ++i) wb4[t + i * NTHR] = src[t + i * NTHR];
        } else if (g >= 16 && g < 32) {     // D: conv_w rows [(g-16)*32, +32)
            const float4* src = reinterpret_cast<const float4*>(conv_w) + (g - 16) * 4096;
#pragma unroll
            for (int i = 0; i < 8; ++i) wb4[t + i * NTHR] = src[t + i * NTHR];
        }
        __syncthreads();
        if (t < C4) {
            float4* shP2 = reinterpret_cast<float4*>(shA);
            float4 a = shP2[t], p1 = shP2[C4 + t], p2 = shP2[2 * C4 + t], p3 = shP2[3 * C4 + t];
            a.x += p1.x + p2.x + p3.x;  a.y += p1.y + p2.y + p3.y;
            a.z += p1.z + p2.z + p3.z;  a.w += p1.w + p2.w + p3.w;
            g_partial[b_own][s_own][t] = a;
        }
    }
    ARRIVE_LINE(&cnt0[b_own]);

    // ================= group A (32..63): Xsum reduce + xr + kp ===============
    if (g >= 32 && g < 64) {
        const int a = g - 32;
        WAIT_LINES(&cnt0[a >> 2], 1, 16);    // only needs its batch's partials
        {   // P2a: float4 outputs o in [a*32, a*32+32), all in batch a>>2
            const int o = a * 32 + (t >> 4), s = t & 15;
            const int bb = o >> 7, cc4 = o & 127;
            float4 v = g_partial[bb][s][cc4];
#pragma unroll
            for (int off = 8; off; off >>= 1) {
                v.x += __shfl_xor_sync(0xffffffffu, v.x, off);
                v.y += __shfl_xor_sync(0xffffffffu, v.y, off);
                v.z += __shfl_xor_sync(0xffffffffu, v.z, off);
                v.w += __shfl_xor_sync(0xffffffffu, v.w, off);
            }
            if (s == 0) g_xsum4[bb][cc4] = v;
        }
        ARRIVE_LINE(&cnt1[a & 3]);
        WAIT_LINES(cnt1, 4, 32);
        {   // P2b: xr rows [a*16,+16) -> shared sXr (not global)
            float4* shA4 = reinterpret_cast<float4*>(shA);
            const float4* gx4 = reinterpret_cast<const float4*>(g_xsum4);
#pragma unroll
            for (int i = 0; i < 2; ++i) shA4[t + i * NTHR] = gx4[t + i * NTHR];
            __syncthreads();

            const int o = a * 16 + warp;
            float acc[Bb];
#pragma unroll
            for (int b = 0; b < Bb; ++b) acc[b] = 0.f;
#pragma unroll
            for (int k = 0; k < 16; ++k) {
                const int c = lane + 32 * k;
                const float wv = wbuf[warp * Cc + c];
#pragma unroll
                for (int b = 0; b < Bb; ++b) acc[b] += wv * shA[b][c];
            }
#pragma unroll
            for (int b = 0; b < Bb; ++b)
#pragma unroll
                for (int off = 16; off; off >>= 1)
                    acc[b] += __shfl_xor_sync(0xffffffffu, acc[b], off);
            if (lane == 0) {
                const float cb = (float)HW * conv_b[o];
#pragma unroll
                for (int b = 0; b < Bb; ++b)
                    sXr[b][warp] = acc[b] + cb + shA[b][o];
            }
        }
        __syncthreads();
        {   // kp[a][b][o] = sum_{cl<16} k_w[o][a*16+cl] * xr[b][cl]  (all o)
            const float* kT = wbuf + 8192;
            const int o = t;
            float acc[Bb];
#pragma unroll
            for (int b = 0; b < Bb; ++b) acc[b] = 0.f;
#pragma unroll
            for (int cl = 0; cl < 16; ++cl) {
                const float kv = kT[cl * Cc + o];
#pragma unroll
                for (int b = 0; b < Bb; ++b) acc[b] += kv * sXr[b][cl];
            }
#pragma unroll
            for (int b = 0; b < Bb; ++b) g_kp[a][b][o] = acc[b];
        }
        ARRIVE_LINE(&cnt2[a & 3]);
    }

    // ================= group C (0..15): Ksum chunk + v + wpart ===============
    if (g < 16) {
        WAIT_LINES(cnt2, 4, 32);
        if (t < 256) {                      // Ks[b][oo] over chunk, + k_b bias
            const int b = t >> 5, oo = t & 31;
            const int o = g * 32 + oo;
            float s = (float)HW * k_b[o];
#pragma unroll
            for (int a = 0; a < 32; ++a) s += g_kp[a][b][o];
            sKs[b][oo] = s;
        }
        __syncthreads();
        if (t < 32) {
            float tot = 0.f;
#pragma unroll
            for (int b = 0; b < Bb; ++b) tot += sKs[b][t];
            sTot[t] = tot;
        }
        __syncthreads();
        if (t < 256) {
            const int b = t >> 5, oo = t & 31;
            sV[b][oo] = sTot[oo] - sKs[b][oo];
        }
        __syncthreads();

        float vreg[Bb];
#pragma unroll
        for (int b = 0; b < Bb; ++b) vreg[b] = sV[b][lane];
        float acc[Bb];
#pragma unroll
        for (int b = 0; b < Bb; ++b) acc[b] = 0.f;
#pragma unroll
        for (int oo = 0; oo < 32; ++oo) {
            const float wv = wbuf[oo * Cc + t];
#pragma unroll
            for (int b = 0; b < Bb; ++b)
                acc[b] += wv * __shfl_sync(0xffffffffu, vreg[b], oo);
        }
#pragma unroll
        for (int b = 0; b < Bb; ++b) g_wpart[g][b][t] = acc[b];
        ARRIVE_LINE(&cnt4[g & 1]);
    }

    // ================= group D (16..31): w reduce (o-chunk) + u partial ======
    if (g >= 16 && g < 32) {
        const int j = g - 16;
        WAIT_LINES(cnt4, 2, 16);
        {   // inline reduce of w over its o-chunk [j*32, +32), all b
            const int p = t >> 1, h = t & 1;       // p: 0..255 = (b,oo)
            const int b = p >> 5, oo = p & 31;
            float s = 0.f;
#pragma unroll
            for (int jj = 0; jj < 8; ++jj)
                s += g_wpart[h * 8 + jj][b][j * 32 + oo];
            s += __shfl_xor_sync(0xffffffffu, s, 1);
            if (h == 0) { shW[b][oo] = s; g_w[b][j * 32 + oo] = s; }
            __syncthreads();
        }
        {   // u partial: conv_w^T over o-chunk
            float acc[Bb];
#pragma unroll
            for (int b = 0; b < Bb; ++b) acc[b] = 0.f;
#pragma unroll
            for (int oo = 0; oo < 32; ++oo) {
                const float wv = wbuf[oo * Cc + t];
#pragma unroll
                for (int b = 0; b < Bb; ++b) acc[b] += wv * shW[b][oo];
            }
#pragma unroll
            for (int b = 0; b < Bb; ++b) g_upart[j][b][t] = acc[b];
        }
        ARRIVE_LINE(&cnt6[0]);
    }

    // ================= all blocks: P6 dot + epilogue =========================
    WAIT_LINES(cnt6, 1, 16);
    {
        // u[t] = sum_j upart[j][b][t] + w[b][t]   (the +w residual term)
        float a = g_w[b_own][t];
#pragma unroll
        for (int jj = 0; jj < 16; ++jj) a += g_upart[jj][b_own][t];
        shB[t] = a;
        __syncthreads();

        const float4 uv = reinterpret_cast<const float4*>(shB)[c4];
#pragma unroll
        for (int p = 0; p < 16; ++p) {
            const float4 xv = xreg[p];
            psum[(rs * 16 + p) * C4 + c4] =
                xv.x * uv.x + xv.y * uv.y + xv.z * uv.z + xv.w * uv.w;
        }
        __syncthreads();

        // row reduce: warp handles 4 rows, 128 partials each
#pragma unroll
        for (int rr = 0; rr < 4; ++rr) {
            const int row = warp * 4 + rr;
            float s = psum[row * C4 + lane] + psum[row * C4 + lane + 32]
                    + psum[row * C4 + lane + 64] + psum[row * C4 + lane + 96];
#pragma unroll
            for (int off = 16; off; off >>= 1)
                s += __shfl_xor_sync(0xffffffffu, s, off);
            if (lane == 0) sdot[row] = s;
        }
    }
    __syncthreads();
    if (warp == 0) {
        float v0 = sdot[lane], v1 = sdot[lane + 32];
        float mn = fminf(v0, v1), mx = fmaxf(v0, v1);
#pragma unroll
        for (int off = 16; off; off >>= 1) {
            mn = fminf(mn, __shfl_xor_sync(0xffffffffu, mn, off));
            mx = fmaxf(mx, __shfl_xor_sync(0xffffffffu, mx, off));
        }
        if (lane == 0) {
            atomicMin(&g_mnk[b_own], enc(mn));
            atomicMax(&g_mxk[b_own], enc(mx));
        }
    }
    ARRIVE_LINE(&cnt7[b_own]);
    WAIT_LINES(&cnt7[b_own], 1, 16);

    if (t < 64) {
        const float mn = dec(g_mnk[b_own]);
        const float mx = dec(g_mxk[b_own]);
        const float inv = 1.0f / (mx - mn);
        const float z = ((sdot[t] - mn) * inv - 0.65f) / 0.15f;
        out[b_own * HW + s_own * 64 + t] = 1.0f / (1.0f + __expf(-z));
    }

    // ======= tail: never-polled reset — 128th arrival resets everything ======
    __syncthreads();
    if (t == 0) {
        unsigned old = atomicAdd(&c_fin.v, 1u);
        if (old == (unsigned)NBLK - 1u) {
#pragma unroll
            for (int i = 0; i < 8;  ++i) { cnt0[i].v = 0u; cnt7[i].v = 0u; }
#pragma unroll
            for (int i = 0; i < 4;  ++i) { cnt1[i].v = 0u; cnt2[i].v = 0u; }
#pragma unroll
            for (int i = 0; i < 2;  ++i) cnt4[i].v = 0u;
            cnt6[0].v = 0u;
            c_fin.v = 0u;
#pragma unroll
            for (int b = 0; b < Bb; ++b) { g_mnk[b] = 0xFFFFFFFFu; g_mxk[b] = 0u; }
            __threadfence();
        }
    }
}

// ---------------------------------------------------------------------------
extern "C" void kernel_launch(void* const* d_in, const int* in_sizes, int n_in,
                              void* d_out, int out_size) {
    const float* x      = (const float*)d_in[0];
    const float* conv_w = (const float*)d_in[1];
    const float* conv_b = (const float*)d_in[2];
    const float* q_w    = (const float*)d_in[3];
    // d_in[4] = q_b: per-batch constant, cancels in min/max normalization.
    const float* k_w    = (const float*)d_in[5];
    const float* k_b    = (const float*)d_in[6];
    float* out = (float*)d_out;

    cudaFuncSetAttribute(fused_kernel,
                         cudaFuncAttributeMaxDynamicSharedMemorySize,
                         DYN_BYTES);
    fused_kernel<<<NBLK, NTHR, DYN_BYTES>>>(x, conv_w, conv_b, q_w, k_w, k_b, out);
}